// round 13
// baseline (speedup 1.0000x reference)
#include <cuda_runtime.h>
#include <cuda_fp16.h>
#include <cstdint>

// ---------------- problem constants ----------------
#define E_EXP   8
#define T_TOK   16384
#define D_MODEL 1024
#define F_FF    4096
#define M_PER_E (T_TOK / E_EXP)   // 2048

// ---------------- scratch (no allocs allowed) ----------------
__device__ __half g_xh [(size_t)T_TOK * D_MODEL];          //  32MB  fp16 X
__device__ __half g_w1t[(size_t)E_EXP * F_FF * D_MODEL];   //  64MB  [E][F][D] fp16
__device__ __half g_w2t[(size_t)E_EXP * D_MODEL * F_FF];   //  64MB  [E][D][F] fp16
__device__ __half g_h  [(size_t)T_TOK * F_FF];             // 128MB  [T][F]    fp16

// ---------------- helpers ----------------
__device__ __forceinline__ uint32_t smem_u32(const void* p) {
    uint32_t a;
    asm("{ .reg .u64 t; cvta.to.shared.u64 t, %1; cvt.u32.u64 %0, t; }" : "=r"(a) : "l"(p));
    return a;
}
#define CP_ASYNC_16(smem_addr, gmem_ptr) \
    asm volatile("cp.async.cg.shared.global [%0], [%1], 16;" \
                 :: "r"(smem_addr), "l"(gmem_ptr) : "memory")
#define CP_COMMIT() asm volatile("cp.async.commit_group;" ::: "memory")
#define CP_WAIT(n)  asm volatile("cp.async.wait_group %0;" :: "n"(n) : "memory")

__device__ __forceinline__ void ldsm_x4(uint32_t* r, uint32_t addr) {
    asm volatile("ldmatrix.sync.aligned.m8n8.x4.shared.b16 {%0,%1,%2,%3}, [%4];"
                 : "=r"(r[0]), "=r"(r[1]), "=r"(r[2]), "=r"(r[3]) : "r"(addr));
}

__device__ __forceinline__ void mma_f16_16n8k16(float* d, const uint32_t* a, const uint32_t* b) {
    asm volatile(
        "mma.sync.aligned.m16n8k16.row.col.f32.f16.f16.f32 "
        "{%0,%1,%2,%3}, {%4,%5,%6,%7}, {%8,%9}, {%0,%1,%2,%3};"
        : "+f"(d[0]), "+f"(d[1]), "+f"(d[2]), "+f"(d[3])
        : "r"(a[0]), "r"(a[1]), "r"(a[2]), "r"(a[3]), "r"(b[0]), "r"(b[1]));
}

// NOTE: libm tanhf deliberately — fast-GELU (__expf) builds consistently lose
// ~10pts of tensor-pipe utilization in the mainloop (R7/R8/R9 vs R6/R10 evidence).
__device__ __forceinline__ float gelu_tanh(float x) {
    float x3 = x * x * x;
    return 0.5f * x * (1.0f + tanhf(0.7978845608028654f * (x + 0.044715f * x3)));
}

// ---------------- prep kernels ----------------
__global__ void cvt_half_kernel(const float* __restrict__ src, __half* __restrict__ dst) {
    size_t i = ((size_t)blockIdx.x * blockDim.x + threadIdx.x) * 4;
    float4 v = *(const float4*)(src + i);
    *(__half2*)(dst + i)     = __floats2half2_rn(v.x, v.y);
    *(__half2*)(dst + i + 2) = __floats2half2_rn(v.z, v.w);
}

// transpose src[z][R][C] fp32 -> dst[z][C][R] fp16, 64x64 tiles, vectorized
__global__ void transpose_cvt_half(const float* __restrict__ src, __half* __restrict__ dst,
                                   int R, int C) {
    __shared__ float t[64][65];
    size_t base = (size_t)blockIdx.z * R * C;
    int c0 = blockIdx.x * 64, r0 = blockIdx.y * 64;
    int tx = threadIdx.x;            // 0..255
    int lr = tx >> 4;                // 0..15
    int lc = tx & 15;                // 0..15
#pragma unroll
    for (int i = 0; i < 4; i++) {    // load 64 rows x 16 float4
        int row = lr + i * 16;
        float4 v = *(const float4*)(src + base + (size_t)(r0 + row) * C + c0 + lc * 4);
        t[row][lc * 4 + 0] = v.x;
        t[row][lc * 4 + 1] = v.y;
        t[row][lc * 4 + 2] = v.z;
        t[row][lc * 4 + 3] = v.w;
    }
    __syncthreads();
#pragma unroll
    for (int i = 0; i < 4; i++) {    // store 64 cols x 16 groups of 4 rows
        int c = lr + i * 16;
        int r4 = lc * 4;
        __half2 h01 = __floats2half2_rn(t[r4 + 0][c], t[r4 + 1][c]);
        __half2 h23 = __floats2half2_rn(t[r4 + 2][c], t[r4 + 3][c]);
        uint2 p;
        p.x = *(uint32_t*)&h01;
        p.y = *(uint32_t*)&h23;
        *(uint2*)(dst + base + (size_t)(c0 + c) * R + r0 + r4) = p;
    }
}

// ---------------- GEMM1: fp16 mma.sync (exact R6/R10 configuration — DO NOT TOUCH) ----
#define BM 128
#define BN 256
#define BK 64
#define NTHREADS 256
#define NSTG 3
#define A_ST (BM * BK * 2)               // 16384 B / stage
#define B_ST (BN * BK * 2)               // 32768 B / stage
#define SM_B_OFF (NSTG * A_ST)           // 49152
#define SMEM_TOTAL (NSTG * (A_ST + B_ST))  // 147456

template <int APPLY_GELU, int OUT_HALF>
__global__ void __launch_bounds__(NTHREADS, 1)
gemm_f16_mma(const __half* __restrict__ A, const __half* __restrict__ Bt,
             const float* __restrict__ bias, void* __restrict__ Cv,
             int K, int N,
             long long aStride, long long bStride, int biasStride, long long cStride) {
    extern __shared__ char smem[];
    const uint32_t sb = smem_u32(smem);
    const int tid = threadIdx.x;
    const int wid = tid >> 5, lane = tid & 31;
    const int g = lane >> 2, tig = lane & 3;
    const int wm = wid & 1, wn = wid >> 1;         // warp grid 2(M) x 4(N)
    const int e  = blockIdx.z;
    const int m0 = blockIdx.y * BM;
    const int n0 = blockIdx.x * BN;

    const __half* Ae = A  + (long long)e * aStride + (long long)m0 * K;
    const __half* Be = Bt + (long long)e * bStride + (long long)n0 * K;
    const float*  be = bias + (long long)e * biasStride + n0;

    const int NK = K / BK;

    auto issue_stage = [&](int kt, int slot) {
        const __half* ag = Ae + kt * BK;
        const __half* bg = Be + kt * BK;
        uint32_t sA = sb + slot * A_ST;
        uint32_t sB = sb + SM_B_OFF + slot * B_ST;
#pragma unroll
        for (int i = 0; i < 4; i++) {                  // A: 1024 x 16B chunks
            int c = tid + i * NTHREADS;
            int row = c >> 3, ch = c & 7;
            CP_ASYNC_16(sA + row * 128 + ((ch ^ (row & 7)) << 4),
                        ag + (long long)row * K + ch * 8);
        }
#pragma unroll
        for (int i = 0; i < 8; i++) {                  // B: 2048 x 16B chunks
            int c = tid + i * NTHREADS;
            int row = c >> 3, ch = c & 7;
            CP_ASYNC_16(sB + row * 128 + ((ch ^ (row & 7)) << 4),
                        bg + (long long)row * K + ch * 8);
        }
    };

    issue_stage(0, 0); CP_COMMIT();
    if (NK > 1) issue_stage(1, 1);
    CP_COMMIT();

    float acc[4][8][4];
#pragma unroll
    for (int mi = 0; mi < 4; mi++)
#pragma unroll
        for (int ni = 0; ni < 8; ni++)
#pragma unroll
            for (int j = 0; j < 4; j++) acc[mi][ni][j] = 0.0f;

    const int aRowL = lane & 15;
    const int aKC   = lane >> 4;
    const int bRowL = ((lane >> 4) << 3) + (lane & 7);
    const int bKC   = (lane >> 3) & 1;
    uint32_t aChunkOff[4], bChunkOff[4];
#pragma unroll
    for (int ks = 0; ks < 4; ks++) {
        aChunkOff[ks] = (uint32_t)(((2 * ks + aKC) ^ (aRowL & 7)) << 4);
        bChunkOff[ks] = (uint32_t)(((2 * ks + bKC) ^ (lane & 7)) << 4);
    }
    uint32_t aRowOff[4], bRowOff[4];
#pragma unroll
    for (int mi = 0; mi < 4; mi++)
        aRowOff[mi] = (uint32_t)((wm * 64 + mi * 16 + aRowL) * 128);
#pragma unroll
    for (int p = 0; p < 4; p++)
        bRowOff[p] = (uint32_t)((wn * 64 + p * 16 + bRowL) * 128);

    for (int kt = 0; kt < NK; ++kt) {
        CP_WAIT(1);
        __syncthreads();
        if (kt + NSTG - 1 < NK) issue_stage(kt + NSTG - 1, (kt + NSTG - 1) % NSTG);
        CP_COMMIT();

        int slot = kt % NSTG;
        uint32_t aBase = sb + slot * A_ST;
        uint32_t bBase = sb + SM_B_OFF + slot * B_ST;

#pragma unroll
        for (int ks = 0; ks < 4; ks++) {               // 4 x K=16 steps
            uint32_t af[4][4], bf[8][2];
#pragma unroll
            for (int mi = 0; mi < 4; mi++)
                ldsm_x4(af[mi], aBase + aRowOff[mi] + aChunkOff[ks]);
#pragma unroll
            for (int p = 0; p < 4; p++) {
                uint32_t r[4];
                ldsm_x4(r, bBase + bRowOff[p] + bChunkOff[ks]);
                bf[2 * p][0] = r[0]; bf[2 * p][1] = r[1];
                bf[2 * p + 1][0] = r[2]; bf[2 * p + 1][1] = r[3];
            }
#pragma unroll
            for (int mi = 0; mi < 4; mi++)
#pragma unroll
                for (int ni = 0; ni < 8; ni++)
                    mma_f16_16n8k16(acc[mi][ni], af[mi], bf[ni]);
        }
    }

#pragma unroll
    for (int ni = 0; ni < 8; ni++) {
        int colL = wn * 64 + ni * 8 + 2 * tig;
        float2 bb = *(const float2*)(be + colL);
#pragma unroll
        for (int mi = 0; mi < 4; mi++) {
            int rowL = m0 + wm * 64 + mi * 16 + g;
            float v0 = acc[mi][ni][0] + bb.x;
            float v1 = acc[mi][ni][1] + bb.y;
            float v2 = acc[mi][ni][2] + bb.x;
            float v3 = acc[mi][ni][3] + bb.y;
            if (APPLY_GELU) {
                v0 = gelu_tanh(v0); v1 = gelu_tanh(v1);
                v2 = gelu_tanh(v2); v3 = gelu_tanh(v3);
            }
            if (OUT_HALF) {
                __half* Ce = (__half*)Cv + (long long)e * cStride;
                __half* p0 = Ce + (long long)rowL * N + n0 + colL;
                *(__half2*)p0 = __floats2half2_rn(v0, v1);
                *(__half2*)(p0 + (long long)8 * N) = __floats2half2_rn(v2, v3);
            } else {
                float* Ce = (float*)Cv + (long long)e * cStride;
                float* p0 = Ce + (long long)rowL * N + n0 + colL;
                *(float2*)p0 = make_float2(v0, v1);
                *(float2*)(p0 + (long long)8 * N) = make_float2(v2, v3);
            }
        }
    }
}

// ---------------- GEMM2: 64x128 tile, 2 CTAs/SM, warp tile 32x32 (FIXED bounds) ----
// Y[M,N] = H[M,K] * W2t[N,K]^T + bias, fp32 out.
// BM2=64, BN2=128, BK=64. 256 threads = 8 warps, warp grid 2(M) x 4(N),
// warp tile 32x32 -> 2 m x 4 n frags (8 HMMA : 4 LDSM per k-step).
// All smem row indices verified in-bounds: A rows <= 63 (64-row stage),
// B rows <= 127 (128-row stage).
// __launch_bounds__(256,2) -> <=128 regs, 2 CTAs/SM for barrier desync.
// grid = 8 n x 32 m x 8 e = 2048 blocks @ 296 concurrent = 6.9 waves.
#define BM2 64
#define BN2 128
#define A2_ST (BM2 * BK * 2)                 // 8192 B / stage
#define B2_ST (BN2 * BK * 2)                 // 16384 B / stage
#define SM2_B_OFF (NSTG * A2_ST)             // 24576
#define SMEM2_TOTAL (NSTG * (A2_ST + B2_ST)) // 73728

__global__ void __launch_bounds__(NTHREADS, 2)
gemm2_f16_mma(const __half* __restrict__ A, const __half* __restrict__ Bt,
              const float* __restrict__ bias, float* __restrict__ Cm,
              int K, int N,
              long long aStride, long long bStride, int biasStride, long long cStride) {
    extern __shared__ char smem[];
    const uint32_t sb = smem_u32(smem);
    const int tid = threadIdx.x;
    const int wid = tid >> 5, lane = tid & 31;
    const int g = lane >> 2, tig = lane & 3;
    const int wm = wid & 1, wn = wid >> 1;         // warp grid 2(M) x 4(N)
    const int e  = blockIdx.z;
    const int m0 = blockIdx.y * BM2;
    const int n0 = blockIdx.x * BN2;

    const __half* Ae = A  + (long long)e * aStride + (long long)m0 * K;
    const __half* Be = Bt + (long long)e * bStride + (long long)n0 * K;
    const float*  be = bias + (long long)e * biasStride + n0;
    float* Ce = Cm + (long long)e * cStride;

    const int NK = K / BK;

    auto issue_stage = [&](int kt, int slot) {
        const __half* ag = Ae + kt * BK;
        const __half* bg = Be + kt * BK;
        uint32_t sA = sb + slot * A2_ST;
        uint32_t sB = sb + SM2_B_OFF + slot * B2_ST;
#pragma unroll
        for (int i = 0; i < 2; i++) {                  // A: 512 x 16B chunks (rows 0..63)
            int c = tid + i * NTHREADS;
            int row = c >> 3, ch = c & 7;
            CP_ASYNC_16(sA + row * 128 + ((ch ^ (row & 7)) << 4),
                        ag + (long long)row * K + ch * 8);
        }
#pragma unroll
        for (int i = 0; i < 4; i++) {                  // B: 1024 x 16B chunks (rows 0..127)
            int c = tid + i * NTHREADS;
            int row = c >> 3, ch = c & 7;
            CP_ASYNC_16(sB + row * 128 + ((ch ^ (row & 7)) << 4),
                        bg + (long long)row * K + ch * 8);
        }
    };

    issue_stage(0, 0); CP_COMMIT();
    if (NK > 1) issue_stage(1, 1);
    CP_COMMIT();

    float acc[2][4][4];
#pragma unroll
    for (int mi = 0; mi < 2; mi++)
#pragma unroll
        for (int ni = 0; ni < 4; ni++)
#pragma unroll
            for (int j = 0; j < 4; j++) acc[mi][ni][j] = 0.0f;

    const int aRowL = lane & 15;
    const int aKC   = lane >> 4;
    const int bRowL = ((lane >> 4) << 3) + (lane & 7);
    const int bKC   = (lane >> 3) & 1;
    uint32_t aChunkOff[4], bChunkOff[4];
#pragma unroll
    for (int ks = 0; ks < 4; ks++) {
        aChunkOff[ks] = (uint32_t)(((2 * ks + aKC) ^ (aRowL & 7)) << 4);
        bChunkOff[ks] = (uint32_t)(((2 * ks + bKC) ^ (lane & 7)) << 4);
    }
    uint32_t aRowOff[2], bRowOff[2];
#pragma unroll
    for (int mi = 0; mi < 2; mi++)
        aRowOff[mi] = (uint32_t)((wm * 32 + mi * 16 + aRowL) * 128);   // rows <= 63
#pragma unroll
    for (int p = 0; p < 2; p++)
        bRowOff[p] = (uint32_t)((wn * 32 + p * 16 + bRowL) * 128);     // rows <= 127

    for (int kt = 0; kt < NK; ++kt) {
        CP_WAIT(1);
        __syncthreads();
        if (kt + NSTG - 1 < NK) issue_stage(kt + NSTG - 1, (kt + NSTG - 1) % NSTG);
        CP_COMMIT();

        int slot = kt % NSTG;
        uint32_t aBase = sb + slot * A2_ST;
        uint32_t bBase = sb + SM2_B_OFF + slot * B2_ST;

#pragma unroll
        for (int ks = 0; ks < 4; ks++) {               // 4 x K=16 steps
            uint32_t af[2][4], bf[4][2];
#pragma unroll
            for (int mi = 0; mi < 2; mi++)
                ldsm_x4(af[mi], aBase + aRowOff[mi] + aChunkOff[ks]);
#pragma unroll
            for (int p = 0; p < 2; p++) {
                uint32_t r[4];
                ldsm_x4(r, bBase + bRowOff[p] + bChunkOff[ks]);
                bf[2 * p][0] = r[0]; bf[2 * p][1] = r[1];
                bf[2 * p + 1][0] = r[2]; bf[2 * p + 1][1] = r[3];
            }
#pragma unroll
            for (int mi = 0; mi < 2; mi++)
#pragma unroll
                for (int ni = 0; ni < 4; ni++)
                    mma_f16_16n8k16(acc[mi][ni], af[mi], bf[ni]);
        }
    }

#pragma unroll
    for (int ni = 0; ni < 4; ni++) {
        int colL = wn * 32 + ni * 8 + 2 * tig;
        float2 bb = *(const float2*)(be + colL);
#pragma unroll
        for (int mi = 0; mi < 2; mi++) {
            int rowL = m0 + wm * 32 + mi * 16 + g;
            float* p0 = Ce + (long long)rowL * N + n0 + colL;
            *(float2*)p0 = make_float2(acc[mi][ni][0] + bb.x, acc[mi][ni][1] + bb.y);
            *(float2*)(p0 + (long long)8 * N) =
                make_float2(acc[mi][ni][2] + bb.x, acc[mi][ni][3] + bb.y);
        }
    }
}

// ---------------- launch ----------------
extern "C" void kernel_launch(void* const* d_in, const int* in_sizes, int n_in,
                              void* d_out, int out_size) {
    (void)in_sizes; (void)n_in; (void)out_size;
    const float* x  = (const float*)d_in[0];
    // d_in[1] = expert_size (uniform T/E by construction; unused)
    const float* w1 = (const float*)d_in[2];
    const float* b1 = (const float*)d_in[3];
    const float* w2 = (const float*)d_in[4];
    const float* b2 = (const float*)d_in[5];
    float* out = (float*)d_out;

    __half *xh, *w1t, *w2t, *h;
    cudaGetSymbolAddress((void**)&xh,  g_xh);
    cudaGetSymbolAddress((void**)&w1t, g_w1t);
    cudaGetSymbolAddress((void**)&w2t, g_w2t);
    cudaGetSymbolAddress((void**)&h,   g_h);

    cudaFuncSetAttribute(gemm_f16_mma<1, 1>,
                         cudaFuncAttributeMaxDynamicSharedMemorySize, SMEM_TOTAL);
    cudaFuncSetAttribute(gemm2_f16_mma,
                         cudaFuncAttributeMaxDynamicSharedMemorySize, SMEM2_TOTAL);

    // prep: convert X, transpose+convert weights (64x64 vectorized tiles)
    cvt_half_kernel<<<(T_TOK * (size_t)D_MODEL) / (256 * 4), 256>>>(x, xh);
    transpose_cvt_half<<<dim3(F_FF / 64, D_MODEL / 64, E_EXP), 256>>>(w1, w1t, D_MODEL, F_FF);
    transpose_cvt_half<<<dim3(D_MODEL / 64, F_FF / 64, E_EXP), 256>>>(w2, w2t, F_FF, D_MODEL);

    // GEMM1: H = half(GELU(X @ W1 + b1))  — BN=256 kernel (R10 exact)
    gemm_f16_mma<1, 1><<<dim3(F_FF / BN, M_PER_E / BM, E_EXP), NTHREADS, SMEM_TOTAL>>>(
        xh, w1t, b1, h,
        /*K=*/D_MODEL, /*N=*/F_FF,
        (long long)M_PER_E * D_MODEL, (long long)F_FF * D_MODEL, F_FF,
        (long long)M_PER_E * F_FF);

    // GEMM2: Y = H @ W2 + b2 (fp32 out) — 64x128 tiles, 2 CTAs/SM, 2048 blocks
    gemm2_f16_mma<<<dim3(D_MODEL / BN2, M_PER_E / BM2, E_EXP), NTHREADS, SMEM2_TOTAL>>>(
        h, w2t, b2, out,
        /*K=*/F_FF, /*N=*/D_MODEL,
        (long long)M_PER_E * F_FF, (long long)D_MODEL * F_FF, D_MODEL,
        (long long)M_PER_E * D_MODEL);
}

// round 14
// speedup vs baseline: 1.0110x; 1.0110x over previous
#include <cuda_runtime.h>
#include <cuda_fp16.h>
#include <cstdint>

// ---------------- problem constants ----------------
#define E_EXP   8
#define T_TOK   16384
#define D_MODEL 1024
#define F_FF    4096
#define M_PER_E (T_TOK / E_EXP)   // 2048

// ---------------- scratch (no allocs allowed) ----------------
__device__ __half g_xh [(size_t)T_TOK * D_MODEL];          //  32MB  fp16 X
__device__ __half g_w1t[(size_t)E_EXP * F_FF * D_MODEL];   //  64MB  [E][F][D] fp16
__device__ __half g_w2t[(size_t)E_EXP * D_MODEL * F_FF];   //  64MB  [E][D][F] fp16
__device__ __half g_h  [(size_t)T_TOK * F_FF];             // 128MB  [T][F]    fp16

// ---------------- helpers ----------------
__device__ __forceinline__ uint32_t smem_u32(const void* p) {
    uint32_t a;
    asm("{ .reg .u64 t; cvta.to.shared.u64 t, %1; cvt.u32.u64 %0, t; }" : "=r"(a) : "l"(p));
    return a;
}
#define CP_ASYNC_16(smem_addr, gmem_ptr) \
    asm volatile("cp.async.cg.shared.global [%0], [%1], 16;" \
                 :: "r"(smem_addr), "l"(gmem_ptr) : "memory")
#define CP_COMMIT() asm volatile("cp.async.commit_group;" ::: "memory")
#define CP_WAIT(n)  asm volatile("cp.async.wait_group %0;" :: "n"(n) : "memory")

__device__ __forceinline__ void ldsm_x4(uint32_t* r, uint32_t addr) {
    asm volatile("ldmatrix.sync.aligned.m8n8.x4.shared.b16 {%0,%1,%2,%3}, [%4];"
                 : "=r"(r[0]), "=r"(r[1]), "=r"(r[2]), "=r"(r[3]) : "r"(addr));
}

__device__ __forceinline__ void mma_f16_16n8k16(float* d, const uint32_t* a, const uint32_t* b) {
    asm volatile(
        "mma.sync.aligned.m16n8k16.row.col.f32.f16.f16.f32 "
        "{%0,%1,%2,%3}, {%4,%5,%6,%7}, {%8,%9}, {%0,%1,%2,%3};"
        : "+f"(d[0]), "+f"(d[1]), "+f"(d[2]), "+f"(d[3])
        : "r"(a[0]), "r"(a[1]), "r"(a[2]), "r"(a[3]), "r"(b[0]), "r"(b[1]));
}

// NOTE: libm tanhf deliberately — fast-GELU (__expf) builds consistently lose
// ~10pts of tensor-pipe utilization in the mainloop (R7/R8/R9 vs R6/R10 evidence).
__device__ __forceinline__ float gelu_tanh(float x) {
    float x3 = x * x * x;
    return 0.5f * x * (1.0f + tanhf(0.7978845608028654f * (x + 0.044715f * x3)));
}

// ---------------- prep kernels ----------------
__global__ void cvt_half_kernel(const float* __restrict__ src, __half* __restrict__ dst) {
    size_t i = ((size_t)blockIdx.x * blockDim.x + threadIdx.x) * 4;
    float4 v = *(const float4*)(src + i);
    *(__half2*)(dst + i)     = __floats2half2_rn(v.x, v.y);
    *(__half2*)(dst + i + 2) = __floats2half2_rn(v.z, v.w);
}

// transpose src[z][R][C] fp32 -> dst[z][C][R] fp16, 64x64 tiles, vectorized
__global__ void transpose_cvt_half(const float* __restrict__ src, __half* __restrict__ dst,
                                   int R, int C) {
    __shared__ float t[64][65];
    size_t base = (size_t)blockIdx.z * R * C;
    int c0 = blockIdx.x * 64, r0 = blockIdx.y * 64;
    int tx = threadIdx.x;            // 0..255
    int lr = tx >> 4;                // 0..15
    int lc = tx & 15;                // 0..15
#pragma unroll
    for (int i = 0; i < 4; i++) {    // load 64 rows x 16 float4
        int row = lr + i * 16;
        float4 v = *(const float4*)(src + base + (size_t)(r0 + row) * C + c0 + lc * 4);
        t[row][lc * 4 + 0] = v.x;
        t[row][lc * 4 + 1] = v.y;
        t[row][lc * 4 + 2] = v.z;
        t[row][lc * 4 + 3] = v.w;
    }
    __syncthreads();
#pragma unroll
    for (int i = 0; i < 4; i++) {    // store 64 cols x 16 groups of 4 rows
        int c = lr + i * 16;
        int r4 = lc * 4;
        __half2 h01 = __floats2half2_rn(t[r4 + 0][c], t[r4 + 1][c]);
        __half2 h23 = __floats2half2_rn(t[r4 + 2][c], t[r4 + 3][c]);
        uint2 p;
        p.x = *(uint32_t*)&h01;
        p.y = *(uint32_t*)&h23;
        *(uint2*)(dst + base + (size_t)(c0 + c) * R + r0 + r4) = p;
    }
}

// ---------------- GEMM1: fp16 mma.sync (exact R6/R10 configuration — DO NOT TOUCH) ----
#define BM 128
#define BN 256
#define BK 64
#define NTHREADS 256
#define NSTG 3
#define A_ST (BM * BK * 2)               // 16384 B / stage
#define B_ST (BN * BK * 2)               // 32768 B / stage
#define SM_B_OFF (NSTG * A_ST)           // 49152
#define SMEM_TOTAL (NSTG * (A_ST + B_ST))  // 147456

template <int APPLY_GELU, int OUT_HALF>
__global__ void __launch_bounds__(NTHREADS, 1)
gemm_f16_mma(const __half* __restrict__ A, const __half* __restrict__ Bt,
             const float* __restrict__ bias, void* __restrict__ Cv,
             int K, int N,
             long long aStride, long long bStride, int biasStride, long long cStride) {
    extern __shared__ char smem[];
    const uint32_t sb = smem_u32(smem);
    const int tid = threadIdx.x;
    const int wid = tid >> 5, lane = tid & 31;
    const int g = lane >> 2, tig = lane & 3;
    const int wm = wid & 1, wn = wid >> 1;         // warp grid 2(M) x 4(N)
    const int e  = blockIdx.z;
    const int m0 = blockIdx.y * BM;
    const int n0 = blockIdx.x * BN;

    const __half* Ae = A  + (long long)e * aStride + (long long)m0 * K;
    const __half* Be = Bt + (long long)e * bStride + (long long)n0 * K;
    const float*  be = bias + (long long)e * biasStride + n0;

    const int NK = K / BK;

    auto issue_stage = [&](int kt, int slot) {
        const __half* ag = Ae + kt * BK;
        const __half* bg = Be + kt * BK;
        uint32_t sA = sb + slot * A_ST;
        uint32_t sB = sb + SM_B_OFF + slot * B_ST;
#pragma unroll
        for (int i = 0; i < 4; i++) {                  // A: 1024 x 16B chunks
            int c = tid + i * NTHREADS;
            int row = c >> 3, ch = c & 7;
            CP_ASYNC_16(sA + row * 128 + ((ch ^ (row & 7)) << 4),
                        ag + (long long)row * K + ch * 8);
        }
#pragma unroll
        for (int i = 0; i < 8; i++) {                  // B: 2048 x 16B chunks
            int c = tid + i * NTHREADS;
            int row = c >> 3, ch = c & 7;
            CP_ASYNC_16(sB + row * 128 + ((ch ^ (row & 7)) << 4),
                        bg + (long long)row * K + ch * 8);
        }
    };

    issue_stage(0, 0); CP_COMMIT();
    if (NK > 1) issue_stage(1, 1);
    CP_COMMIT();

    float acc[4][8][4];
#pragma unroll
    for (int mi = 0; mi < 4; mi++)
#pragma unroll
        for (int ni = 0; ni < 8; ni++)
#pragma unroll
            for (int j = 0; j < 4; j++) acc[mi][ni][j] = 0.0f;

    const int aRowL = lane & 15;
    const int aKC   = lane >> 4;
    const int bRowL = ((lane >> 4) << 3) + (lane & 7);
    const int bKC   = (lane >> 3) & 1;
    uint32_t aChunkOff[4], bChunkOff[4];
#pragma unroll
    for (int ks = 0; ks < 4; ks++) {
        aChunkOff[ks] = (uint32_t)(((2 * ks + aKC) ^ (aRowL & 7)) << 4);
        bChunkOff[ks] = (uint32_t)(((2 * ks + bKC) ^ (lane & 7)) << 4);
    }
    uint32_t aRowOff[4], bRowOff[4];
#pragma unroll
    for (int mi = 0; mi < 4; mi++)
        aRowOff[mi] = (uint32_t)((wm * 64 + mi * 16 + aRowL) * 128);
#pragma unroll
    for (int p = 0; p < 4; p++)
        bRowOff[p] = (uint32_t)((wn * 64 + p * 16 + bRowL) * 128);

    for (int kt = 0; kt < NK; ++kt) {
        CP_WAIT(1);
        __syncthreads();
        if (kt + NSTG - 1 < NK) issue_stage(kt + NSTG - 1, (kt + NSTG - 1) % NSTG);
        CP_COMMIT();

        int slot = kt % NSTG;
        uint32_t aBase = sb + slot * A_ST;
        uint32_t bBase = sb + SM_B_OFF + slot * B_ST;

#pragma unroll
        for (int ks = 0; ks < 4; ks++) {               // 4 x K=16 steps
            uint32_t af[4][4], bf[8][2];
#pragma unroll
            for (int mi = 0; mi < 4; mi++)
                ldsm_x4(af[mi], aBase + aRowOff[mi] + aChunkOff[ks]);
#pragma unroll
            for (int p = 0; p < 4; p++) {
                uint32_t r[4];
                ldsm_x4(r, bBase + bRowOff[p] + bChunkOff[ks]);
                bf[2 * p][0] = r[0]; bf[2 * p][1] = r[1];
                bf[2 * p + 1][0] = r[2]; bf[2 * p + 1][1] = r[3];
            }
#pragma unroll
            for (int mi = 0; mi < 4; mi++)
#pragma unroll
                for (int ni = 0; ni < 8; ni++)
                    mma_f16_16n8k16(acc[mi][ni], af[mi], bf[ni]);
        }
    }

#pragma unroll
    for (int ni = 0; ni < 8; ni++) {
        int colL = wn * 64 + ni * 8 + 2 * tig;
        float2 bb = *(const float2*)(be + colL);
#pragma unroll
        for (int mi = 0; mi < 4; mi++) {
            int rowL = m0 + wm * 64 + mi * 16 + g;
            float v0 = acc[mi][ni][0] + bb.x;
            float v1 = acc[mi][ni][1] + bb.y;
            float v2 = acc[mi][ni][2] + bb.x;
            float v3 = acc[mi][ni][3] + bb.y;
            if (APPLY_GELU) {
                v0 = gelu_tanh(v0); v1 = gelu_tanh(v1);
                v2 = gelu_tanh(v2); v3 = gelu_tanh(v3);
            }
            if (OUT_HALF) {
                __half* Ce = (__half*)Cv + (long long)e * cStride;
                __half* p0 = Ce + (long long)rowL * N + n0 + colL;
                *(__half2*)p0 = __floats2half2_rn(v0, v1);
                *(__half2*)(p0 + (long long)8 * N) = __floats2half2_rn(v2, v3);
            } else {
                float* Ce = (float*)Cv + (long long)e * cStride;
                float* p0 = Ce + (long long)rowL * N + n0 + colL;
                *(float2*)p0 = make_float2(v0, v1);
                *(float2*)(p0 + (long long)8 * N) = make_float2(v2, v3);
            }
        }
    }
}

// ---------------- GEMM2: exact R11 configuration (best measured) ----------------
// Y[M,N] = H[M,K] * W2t[N,K]^T + bias, fp32 out, no GELU.
// BM=128, BN2=128, BK=64. 256 threads = 8 warps, warp grid 2(M) x 4(N),
// warp tile 64x32 -> 4 m x 4 n frags. grid = 8 n x 16 m x 8 e = 1024 blocks (~7 waves).
#define BN2 128
#define B2_ST (BN2 * BK * 2)               // 16384 B / stage
#define SM2_B_OFF (NSTG * A_ST)            // 49152
#define SMEM2_TOTAL (NSTG * (A_ST + B2_ST))  // 98304

__global__ void __launch_bounds__(NTHREADS, 1)
gemm2_f16_mma(const __half* __restrict__ A, const __half* __restrict__ Bt,
              const float* __restrict__ bias, float* __restrict__ Cm,
              int K, int N,
              long long aStride, long long bStride, int biasStride, long long cStride) {
    extern __shared__ char smem[];
    const uint32_t sb = smem_u32(smem);
    const int tid = threadIdx.x;
    const int wid = tid >> 5, lane = tid & 31;
    const int g = lane >> 2, tig = lane & 3;
    const int wm = wid & 1, wn = wid >> 1;         // warp grid 2(M) x 4(N)
    const int e  = blockIdx.z;
    const int m0 = blockIdx.y * BM;
    const int n0 = blockIdx.x * BN2;

    const __half* Ae = A  + (long long)e * aStride + (long long)m0 * K;
    const __half* Be = Bt + (long long)e * bStride + (long long)n0 * K;
    const float*  be = bias + (long long)e * biasStride + n0;
    float* Ce = Cm + (long long)e * cStride;

    const int NK = K / BK;

    auto issue_stage = [&](int kt, int slot) {
        const __half* ag = Ae + kt * BK;
        const __half* bg = Be + kt * BK;
        uint32_t sA = sb + slot * A_ST;
        uint32_t sB = sb + SM2_B_OFF + slot * B2_ST;
#pragma unroll
        for (int i = 0; i < 4; i++) {                  // A: 1024 x 16B chunks
            int c = tid + i * NTHREADS;
            int row = c >> 3, ch = c & 7;
            CP_ASYNC_16(sA + row * 128 + ((ch ^ (row & 7)) << 4),
                        ag + (long long)row * K + ch * 8);
        }
#pragma unroll
        for (int i = 0; i < 4; i++) {                  // B: 1024 x 16B chunks
            int c = tid + i * NTHREADS;
            int row = c >> 3, ch = c & 7;
            CP_ASYNC_16(sB + row * 128 + ((ch ^ (row & 7)) << 4),
                        bg + (long long)row * K + ch * 8);
        }
    };

    issue_stage(0, 0); CP_COMMIT();
    if (NK > 1) issue_stage(1, 1);
    CP_COMMIT();

    float acc[4][4][4];
#pragma unroll
    for (int mi = 0; mi < 4; mi++)
#pragma unroll
        for (int ni = 0; ni < 4; ni++)
#pragma unroll
            for (int j = 0; j < 4; j++) acc[mi][ni][j] = 0.0f;

    const int aRowL = lane & 15;
    const int aKC   = lane >> 4;
    const int bRowL = ((lane >> 4) << 3) + (lane & 7);
    const int bKC   = (lane >> 3) & 1;
    uint32_t aChunkOff[4], bChunkOff[4];
#pragma unroll
    for (int ks = 0; ks < 4; ks++) {
        aChunkOff[ks] = (uint32_t)(((2 * ks + aKC) ^ (aRowL & 7)) << 4);
        bChunkOff[ks] = (uint32_t)(((2 * ks + bKC) ^ (lane & 7)) << 4);
    }
    uint32_t aRowOff[4], bRowOff[2];
#pragma unroll
    for (int mi = 0; mi < 4; mi++)
        aRowOff[mi] = (uint32_t)((wm * 64 + mi * 16 + aRowL) * 128);
#pragma unroll
    for (int p = 0; p < 2; p++)
        bRowOff[p] = (uint32_t)((wn * 32 + p * 16 + bRowL) * 128);

    for (int kt = 0; kt < NK; ++kt) {
        CP_WAIT(1);
        __syncthreads();
        if (kt + NSTG - 1 < NK) issue_stage(kt + NSTG - 1, (kt + NSTG - 1) % NSTG);
        CP_COMMIT();

        int slot = kt % NSTG;
        uint32_t aBase = sb + slot * A_ST;
        uint32_t bBase = sb + SM2_B_OFF + slot * B2_ST;

#pragma unroll
        for (int ks = 0; ks < 4; ks++) {               // 4 x K=16 steps
            uint32_t af[4][4], bf[4][2];
#pragma unroll
            for (int mi = 0; mi < 4; mi++)
                ldsm_x4(af[mi], aBase + aRowOff[mi] + aChunkOff[ks]);
#pragma unroll
            for (int p = 0; p < 2; p++) {
                uint32_t r[4];
                ldsm_x4(r, bBase + bRowOff[p] + bChunkOff[ks]);
                bf[2 * p][0] = r[0]; bf[2 * p][1] = r[1];
                bf[2 * p + 1][0] = r[2]; bf[2 * p + 1][1] = r[3];
            }
#pragma unroll
            for (int mi = 0; mi < 4; mi++)
#pragma unroll
                for (int ni = 0; ni < 4; ni++)
                    mma_f16_16n8k16(acc[mi][ni], af[mi], bf[ni]);
        }
    }

#pragma unroll
    for (int ni = 0; ni < 4; ni++) {
        int colL = wn * 32 + ni * 8 + 2 * tig;
        float2 bb = *(const float2*)(be + colL);
#pragma unroll
        for (int mi = 0; mi < 4; mi++) {
            int rowL = m0 + wm * 64 + mi * 16 + g;
            float* p0 = Ce + (long long)rowL * N + n0 + colL;
            *(float2*)p0 = make_float2(acc[mi][ni][0] + bb.x, acc[mi][ni][1] + bb.y);
            *(float2*)(p0 + (long long)8 * N) =
                make_float2(acc[mi][ni][2] + bb.x, acc[mi][ni][3] + bb.y);
        }
    }
}

// ---------------- launch ----------------
extern "C" void kernel_launch(void* const* d_in, const int* in_sizes, int n_in,
                              void* d_out, int out_size) {
    (void)in_sizes; (void)n_in; (void)out_size;
    const float* x  = (const float*)d_in[0];
    // d_in[1] = expert_size (uniform T/E by construction; unused)
    const float* w1 = (const float*)d_in[2];
    const float* b1 = (const float*)d_in[3];
    const float* w2 = (const float*)d_in[4];
    const float* b2 = (const float*)d_in[5];
    float* out = (float*)d_out;

    __half *xh, *w1t, *w2t, *h;
    cudaGetSymbolAddress((void**)&xh,  g_xh);
    cudaGetSymbolAddress((void**)&w1t, g_w1t);
    cudaGetSymbolAddress((void**)&w2t, g_w2t);
    cudaGetSymbolAddress((void**)&h,   g_h);

    cudaFuncSetAttribute(gemm_f16_mma<1, 1>,
                         cudaFuncAttributeMaxDynamicSharedMemorySize, SMEM_TOTAL);
    cudaFuncSetAttribute(gemm2_f16_mma,
                         cudaFuncAttributeMaxDynamicSharedMemorySize, SMEM2_TOTAL);

    // Side stream + events, created once on the first (non-captured) correctness
    // call; reused unchanged in every subsequent call so the captured graph is
    // identical each time. Host-object caching only — no device memory involved.
    static cudaStream_t s_side = nullptr;
    static cudaEvent_t  ev_fork = nullptr, ev_join = nullptr;
    if (s_side == nullptr) {
        cudaStreamCreateWithFlags(&s_side, cudaStreamNonBlocking);
        cudaEventCreateWithFlags(&ev_fork, cudaEventDisableTiming);
        cudaEventCreateWithFlags(&ev_join, cudaEventDisableTiming);
    }

    // prep on main stream: convert X, transpose w1
    cvt_half_kernel<<<(T_TOK * (size_t)D_MODEL) / (256 * 4), 256>>>(x, xh);
    transpose_cvt_half<<<dim3(F_FF / 64, D_MODEL / 64, E_EXP), 256>>>(w1, w1t, D_MODEL, F_FF);

    // fork: w2 transpose runs concurrently with GEMM1 (GEMM1 is compute-bound,
    // the transpose is bandwidth-bound — complementary)
    cudaEventRecord(ev_fork, 0);
    cudaStreamWaitEvent(s_side, ev_fork, 0);
    transpose_cvt_half<<<dim3(D_MODEL / 64, F_FF / 64, E_EXP), 256, 0, s_side>>>(
        w2, w2t, F_FF, D_MODEL);
    cudaEventRecord(ev_join, s_side);

    // GEMM1: H = half(GELU(X @ W1 + b1))  — BN=256 kernel (R10 exact)
    gemm_f16_mma<1, 1><<<dim3(F_FF / BN, M_PER_E / BM, E_EXP), NTHREADS, SMEM_TOTAL>>>(
        xh, w1t, b1, h,
        /*K=*/D_MODEL, /*N=*/F_FF,
        (long long)M_PER_E * D_MODEL, (long long)F_FF * D_MODEL, F_FF,
        (long long)M_PER_E * F_FF);

    // join: GEMM2 needs w2t
    cudaStreamWaitEvent(0, ev_join, 0);

    // GEMM2: Y = H @ W2 + b2 (fp32 out) — BN=128 kernel (R11 exact)
    gemm2_f16_mma<<<dim3(D_MODEL / BN2, M_PER_E / BM, E_EXP), NTHREADS, SMEM2_TOTAL>>>(
        h, w2t, b2, out,
        /*K=*/F_FF, /*N=*/D_MODEL,
        (long long)M_PER_E * F_FF, (long long)D_MODEL * F_FF, D_MODEL,
        (long long)M_PER_E * D_MODEL);
}